// round 15
// baseline (speedup 1.0000x reference)
#include <cuda_runtime.h>

#define D 128
#define BATCH 1024
#define SEQ 200
#define TSTEPS 199   // S-1

#define NQ 50000
#define NC 1000
#define NQD 101
#define NCD 101

typedef unsigned long long ull;

// ---------------- device scratch ----------------
__device__ float g_Tq_x[NQ * D];
__device__ float g_Tc_x[NC * D];
__device__ float g_Tqd_x[NQD * D];
__device__ float g_Tcd_x[NCD * D];
__device__ float g_TqA1[NQ * D];
__device__ float g_TqA2[NQ * D];
__device__ float g_TcA1[NC * D];
__device__ float g_TcA2[NC * D];
__device__ float g_TqdA1[NQD * D];
__device__ float g_TqdA2[NQD * D];
__device__ float g_TcdA1[NCD * D];
__device__ float g_TcdA2[NCD * D];
__device__ float g_Tcorr_p1[2 * D];
__device__ float g_Tcorr_p2[2 * D];
__device__ float g_Tcorr_k[2 * D];
__device__ float g_Tqd_k[NQD * D];
__device__ float g_Tcd_k[NCD * D];
// composed weights: Wc[z][n][c] = (Wsz @ Wx)[n][c]
__device__ float g_Wc[2 * 128 * 512];
// composed biases
__device__ float g_bc[2 * 128];
// dense pre-gathered scan inputs [t][b][d]
__device__ float g_A1[(size_t)TSTEPS * BATCH * D];
__device__ float g_A2[(size_t)TSTEPS * BATCH * D];
__device__ float g_Ck[(size_t)TSTEPS * BATCH * D];
__device__ float g_Xn[(size_t)TSTEPS * BATCH * D];
// packed k-major interleaved [Wp1a;Wp2a]: (n,k) at float[(k>>2)*1024 + n*4 + (k&3)]
__device__ float g_W2p[256 * D];

// ---------------- f32x2 helpers ----------------
__device__ __forceinline__ void ffma2(ull& acc, ull a, ull b) {
    asm("fma.rn.f32x2 %0, %1, %2, %0;" : "+l"(acc) : "l"(a), "l"(b));
}
__device__ __forceinline__ float unpack_sum(ull v) {
    float lo, hi;
    asm("mov.b64 {%0,%1}, %2;" : "=f"(lo), "=f"(hi) : "l"(v));
    return lo + hi;
}

// ---------------- math helpers ----------------
__device__ __forceinline__ float sigmoidf_(float x) {
    return __fdividef(1.0f, 1.0f + __expf(-x));
}
__device__ __forceinline__ float tanhf_(float x) {
    x = fminf(fmaxf(x, -15.0f), 15.0f);
    float e = __expf(2.0f * x);
    return __fdividef(e - 1.0f, e + 1.0f);
}

// ---------------- compose kernels ----------------
__global__ void __launch_bounds__(128) compose_w(
    const float* __restrict__ Ws1, const float* __restrict__ Ws2,
    const float* __restrict__ Wx)
{
    const float* Ws = blockIdx.z ? Ws2 : Ws1;
    float* out = g_Wc + (size_t)blockIdx.z * 128 * 512;
    int n = blockIdx.y;
    int c = blockIdx.x * 128 + threadIdx.x;
    float s = 0.0f;
#pragma unroll 8
    for (int i = 0; i < 128; i++)
        s = fmaf(Ws[n * 128 + i], Wx[i * 512 + c], s);
    out[n * 512 + c] = s;
}

__global__ void compose_bias(
    const float* __restrict__ Ws1, const float* __restrict__ Ws2,
    const float* __restrict__ bx,
    const float* __restrict__ bs1, const float* __restrict__ bs2)
{
    int tid = threadIdx.x;  // 256
    const float* Ws = (tid < 128) ? Ws1 : Ws2;
    const float* bs = (tid < 128) ? bs1 : bs2;
    int n = tid & 127;
    float s = bs[n];
#pragma unroll 8
    for (int i = 0; i < 128; i++)
        s = fmaf(Ws[n * 128 + i], bx[i], s);
    g_bc[tid] = s;
}

// ---------------- fused table GEMMs (17 jobs, one launch) ----------------
struct JobTable {
    const float* E[17];
    const float* W[17];
    const float* bias[17];
    float*       out[17];
    int          ld[17];
    int          rows[17];
    int          blk0[18];
};

__global__ void __launch_bounds__(128) tables_all(JobTable jt)
{
    int j = 0;
    while ((int)blockIdx.x >= jt.blk0[j + 1]) j++;
    int lb = blockIdx.x - jt.blk0[j];

    const float* E = jt.E[j];
    const float* W = jt.W[j];
    const float* bias = jt.bias[j];
    float* out = jt.out[j];
    int ldW = jt.ld[j];
    int nrows = jt.rows[j];

    extern __shared__ float sm[];
    float* sW = sm;                 // [128][132]
    float* sE = sm + 128 * 132;     // [32][128]
    int tid = threadIdx.x;
    int r0 = lb * 32;
    int rows = nrows - r0; if (rows > 32) rows = 32;

    for (int i = tid; i < 128 * 128; i += 128) {
        int n = i >> 7, k = i & 127;
        sW[n * 132 + k] = W[(size_t)n * ldW + k];
    }
    for (int i = tid; i < rows * 128; i += 128) {
        int m = i >> 7, k = i & 127;
        sE[m * 128 + k] = E[(size_t)(r0 + m) * 128 + k];
    }
    for (int i = tid + rows * 128; i < 32 * 128; i += 128) sE[i] = 0.0f;
    __syncthreads();

    ull acc[32];
#pragma unroll
    for (int m = 0; m < 32; m++) acc[m] = 0ull;

    const ulonglong2* wr = reinterpret_cast<const ulonglong2*>(sW + tid * 132);
#pragma unroll 2
    for (int kc = 0; kc < 32; kc++) {
        ulonglong2 w = wr[kc];
#pragma unroll
        for (int m = 0; m < 32; m++) {
            ulonglong2 e = reinterpret_cast<const ulonglong2*>(sE + m * 128)[kc];
            ffma2(acc[m], e.x, w.x);
            ffma2(acc[m], e.y, w.y);
        }
    }
    float b = (bias != nullptr) ? bias[tid] : 0.0f;
    for (int m = 0; m < rows; m++)
        out[(size_t)(r0 + m) * 128 + tid] = unpack_sum(acc[m]) + b;
}

// ---------------- pack [Wp1a;Wp2a] ----------------
__global__ void pack_w2(const float* __restrict__ Wp1, const float* __restrict__ Wp2)
{
    int i = blockIdx.x * 256 + threadIdx.x;     // 32768 total
    if (i >= 256 * 128) return;
    int n = i >> 7, k = i & 127;
    float v = (n < 128) ? Wp1[n * 256 + k] : Wp2[(n - 128) * 256 + k];
    g_W2p[(k >> 2) * 1024 + n * 4 + (k & 3)] = v;
}

// ---------------- pre-gather dense scan inputs ----------------
__global__ void __launch_bounds__(128) pregather(
    const int* __restrict__ q, const int* __restrict__ c,
    const int* __restrict__ qd, const int* __restrict__ cd,
    const int* __restrict__ corr)
{
    int b = blockIdx.x, t = blockIdx.y, d = threadIdx.x;
    int base = b * SEQ + t;
    int iq = q[base], ic = c[base], iqd = qd[base], icd = cd[base], ico = corr[base];
    int iq2 = q[base + 1], ic2 = c[base + 1], iqd2 = qd[base + 1], icd2 = cd[base + 1];
    size_t o = ((size_t)t * BATCH + b) * D + d;
    g_A1[o] = g_TqA1[iq * D + d] + g_TcA1[ic * D + d] + g_TqdA1[iqd * D + d] + g_TcdA1[icd * D + d];
    g_A2[o] = g_TqA2[iq * D + d] + g_TcA2[ic * D + d] + g_TqdA2[iqd * D + d] + g_TcdA2[icd * D + d];
    g_Ck[o] = g_Tcorr_k[ico * D + d] + g_Tqd_k[iqd * D + d] + g_Tcd_k[icd * D + d];
    g_Xn[o] = g_Tq_x[iq2 * D + d] + g_Tc_x[ic2 * D + d] + g_Tqd_x[iqd2 * D + d] + g_Tcd_x[icd2 * D + d];
}

// ---------------- sequential scan ----------------
// grid 148: CTAs 0..143 -> 7 batch rows, 144..147 -> 4. 384 threads.
// dyn smem: [Ws1; Ws2; Wk1] as [384][132] fp32.
// Phase1 (384 thr): [U(256) | G(128)] = h @ [Ws1;Ws2;Wk1]^T
// EW    (384 thr): sdf, spread over all elements
// Phase2 (256 thr): V(256) = sdf @ [Wp1a;Wp2a]^T (rolling L2 stream)
// Finalize: warp-per-row, shuffle-reduced y dot.

template<int M>
__device__ __forceinline__ void scan_loop(
    const float* __restrict__ smw,
    float (*sh_h)[128], float (*sh_sdf)[128], float (*sh_U)[384],
    float (*sh_cp1)[128], float (*sh_cp2)[128], int* sh_ci,
    int b0, const int* __restrict__ corr_seq,
    const float* __restrict__ h0, float* __restrict__ y)
{
    const int tid = threadIdx.x;
    const int warp = tid >> 5, lane = tid & 31;
    const bool is_p2 = (tid < 256);
    const bool is_fin = (warp < M);
    const ulonglong2* wp = reinterpret_cast<const ulonglong2*>(g_W2p);

    // ew element mapping: e in {tid, tid+384, tid+768}, valid while e < M*128
    int eoff[3]; bool ev[3];
#pragma unroll
    for (int i = 0; i < 3; i++) {
        int e = tid + i * 384;
        ev[i] = (e < M * 128);
        int em = e >> 7, ed = e & 127;
        eoff[i] = (b0 + em) * 128 + ed;
    }
    // finalize mapping: warp = m, lane covers d = lane + 32j
    int foff[4];
#pragma unroll
    for (int j = 0; j < 4; j++)
        foff[j] = (b0 + warp) * 128 + lane + 32 * j;

    for (int i = tid; i < M * 128; i += 384) {
        int m = i >> 7, k = i & 127;
        sh_h[m][k] = h0[(size_t)(b0 + m) * 128 + k];
    }
    if (tid < M) y[(b0 + tid) * SEQ + (SEQ - 1)] = 0.0f;
    __syncthreads();

    for (int t = 0; t < TSTEPS; t++) {
        const size_t tb = (size_t)t * (BATCH * D);
        // ---- stream prefetch (no smem deps; hidden behind phase1)
        float a1v[3], a2v[3];
#pragma unroll
        for (int i = 0; i < 3; i++) if (ev[i]) {
            a1v[i] = g_A1[tb + eoff[i]];
            a2v[i] = g_A2[tb + eoff[i]];
        }
        float ckv[4], xnv[4];
        if (is_fin) {
#pragma unroll
            for (int j = 0; j < 4; j++) {
                ckv[j] = g_Ck[tb + foff[j]];
                xnv[j] = g_Xn[tb + foff[j]];
            }
        }
        if (tid < M) sh_ci[tid] = corr_seq[(b0 + tid) * SEQ + t];

        // ---- Phase1: col = tid over [Ws1;Ws2;Wk1]
        {
            ull acc[M];
#pragma unroll
            for (int m = 0; m < M; m++) acc[m] = 0ull;
            const ulonglong2* wr = reinterpret_cast<const ulonglong2*>(smw + tid * 132);
#pragma unroll 4
            for (int kc = 0; kc < 32; kc++) {
                ulonglong2 w = wr[kc];
#pragma unroll
                for (int m = 0; m < M; m++) {
                    ulonglong2 h2 = reinterpret_cast<const ulonglong2*>(&sh_h[m][0])[kc];
                    ffma2(acc[m], h2.x, w.x);
                    ffma2(acc[m], h2.y, w.y);
                }
            }
#pragma unroll
            for (int m = 0; m < M; m++) sh_U[m][tid] = unpack_sum(acc[m]);
        }
        __syncthreads();

        // ---- EW: sdf over all elements, all threads
#pragma unroll
        for (int i = 0; i < 3; i++) if (ev[i]) {
            int e = tid + i * 384;
            int em = e >> 7, ed = e & 127;
            float s1 = a1v[i] - sh_U[em][ed];
            float s2 = a2v[i] - sh_U[em][ed + 128];
            sh_sdf[em][ed] = sigmoidf_(s1) * tanhf_(s2);
        }
        __syncthreads();

        // ---- Phase2: 256 threads, rolling depth-4 L2 pipeline over W2p
        if (is_p2) {
            ull acc[M];
#pragma unroll
            for (int m = 0; m < M; m++) acc[m] = 0ull;
            ulonglong2 pf[4];
#pragma unroll
            for (int i = 0; i < 4; i++) pf[i] = wp[i * 256 + tid];
#pragma unroll 4
            for (int kc = 0; kc < 32; kc++) {
                ulonglong2 w = pf[kc & 3];
                if (kc < 28) pf[kc & 3] = wp[(kc + 4) * 256 + tid];
#pragma unroll
                for (int m = 0; m < M; m++) {
                    ulonglong2 s2 = reinterpret_cast<const ulonglong2*>(&sh_sdf[m][0])[kc];
                    ffma2(acc[m], s2.x, w.x);
                    ffma2(acc[m], s2.y, w.y);
                }
            }
#pragma unroll
            for (int m = 0; m < M; m++) sh_U[m][tid] = unpack_sum(acc[m]);  // V in U[0:256)
        }
        __syncthreads();

        // ---- Finalize: warp-per-row, 4-way ILP, shuffle reduce
        if (is_fin) {
            const int m = warp;
            const int ci = sh_ci[m];
            float part = 0.0f;
#pragma unroll
            for (int j = 0; j < 4; j++) {
                int d = lane + 32 * j;
                float g   = sigmoidf_(ckv[j] + sh_U[m][d + 256]);
                float p1  = sh_cp1[ci][d] + sh_U[m][d];
                float p2  = sh_cp2[ci][d] + sh_U[m][d + 128];
                float pka = sigmoidf_(p1) * tanhf_(p2);
                float hnew = g * sh_h[m][d] + (1.0f - g) * pka;
                sh_h[m][d] = hnew;
                part = fmaf(xnv[j], hnew, part);
            }
#pragma unroll
            for (int off = 16; off; off >>= 1)
                part += __shfl_down_sync(0xffffffffu, part, off);
            if (lane == 0)
                y[(b0 + m) * SEQ + t] = sigmoidf_(part);
        }
        __syncthreads();
    }
}

__global__ void __launch_bounds__(384, 1) scan_kernel(
    const float* __restrict__ Ws1, const float* __restrict__ Ws2,
    const float* __restrict__ Wk,  const int* __restrict__ corr_seq,
    const float* __restrict__ h0,  float* __restrict__ y)
{
    extern __shared__ float smw[];                       // [384][132]
    __shared__ __align__(16) float sh_h[7][128];
    __shared__ __align__(16) float sh_sdf[7][128];
    __shared__ __align__(16) float sh_U[7][384];
    __shared__ __align__(16) float sh_cp1[2][128];
    __shared__ __align__(16) float sh_cp2[2][128];
    __shared__ int   sh_ci[7];

    int tid = threadIdx.x;
    // weights: rows 0-127 Ws1, 128-255 Ws2, 256-383 Wk[:,0:128]
    for (int i = tid; i < 384 * 128; i += 384) {
        int n = i >> 7, k = i & 127;
        float v;
        if (n < 128)      v = Ws1[n * 128 + k];
        else if (n < 256) v = Ws2[(n - 128) * 128 + k];
        else              v = Wk[(n - 256) * 512 + k];
        smw[n * 132 + k] = v;
    }
    for (int i = tid; i < 256; i += 384) {
        ((float*)sh_cp1)[i] = g_Tcorr_p1[i];
        ((float*)sh_cp2)[i] = g_Tcorr_p2[i];
    }
    // __syncthreads happens inside scan_loop after h0 load.

    if (blockIdx.x < 144)
        scan_loop<7>(smw, sh_h, sh_sdf, sh_U, sh_cp1, sh_cp2, sh_ci,
                     blockIdx.x * 7, corr_seq, h0, y);
    else
        scan_loop<4>(smw, sh_h, sh_sdf, sh_U, sh_cp1, sh_cp2, sh_ci,
                     1008 + (blockIdx.x - 144) * 4, corr_seq, h0, y);
}

// ---------------- host launch ----------------
extern "C" void kernel_launch(void* const* d_in, const int* in_sizes, int n_in,
                              void* d_out, int out_size)
{
    const int*   qseq  = (const int*)  d_in[0];
    const int*   cseq  = (const int*)  d_in[1];
    const int*   qdseq = (const int*)  d_in[2];
    const int*   cdseq = (const int*)  d_in[3];
    const int*   coseq = (const int*)  d_in[4];
    const float* Eq    = (const float*)d_in[5];
    const float* Ec    = (const float*)d_in[6];
    const float* Eqd   = (const float*)d_in[7];
    const float* Ecd   = (const float*)d_in[8];
    const float* Ecorr = (const float*)d_in[9];
    const float* Wx    = (const float*)d_in[10];
    const float* bx    = (const float*)d_in[11];
    const float* Ws1   = (const float*)d_in[12];
    const float* bs1   = (const float*)d_in[13];
    const float* Ws2   = (const float*)d_in[14];
    const float* bs2   = (const float*)d_in[15];
    const float* Wp1   = (const float*)d_in[16];
    const float* bp1   = (const float*)d_in[17];
    const float* Wp2   = (const float*)d_in[18];
    const float* bp2   = (const float*)d_in[19];
    const float* Wk    = (const float*)d_in[20];
    const float* bk    = (const float*)d_in[21];
    const float* h0    = (const float*)d_in[22];
    float* y = (float*)d_out;

    float *Tq_x, *Tc_x, *Tqd_x, *Tcd_x;
    float *TqA1, *TqA2, *TcA1, *TcA2, *TqdA1, *TqdA2, *TcdA1, *TcdA2;
    float *Tcp1, *Tcp2, *Tck, *Tqdk, *Tcdk, *Wc, *bc;
    cudaGetSymbolAddress((void**)&Tq_x, g_Tq_x);
    cudaGetSymbolAddress((void**)&Tc_x, g_Tc_x);
    cudaGetSymbolAddress((void**)&Tqd_x, g_Tqd_x);
    cudaGetSymbolAddress((void**)&Tcd_x, g_Tcd_x);
    cudaGetSymbolAddress((void**)&TqA1, g_TqA1);
    cudaGetSymbolAddress((void**)&TqA2, g_TqA2);
    cudaGetSymbolAddress((void**)&TcA1, g_TcA1);
    cudaGetSymbolAddress((void**)&TcA2, g_TcA2);
    cudaGetSymbolAddress((void**)&TqdA1, g_TqdA1);
    cudaGetSymbolAddress((void**)&TqdA2, g_TqdA2);
    cudaGetSymbolAddress((void**)&TcdA1, g_TcdA1);
    cudaGetSymbolAddress((void**)&TcdA2, g_TcdA2);
    cudaGetSymbolAddress((void**)&Tcp1, g_Tcorr_p1);
    cudaGetSymbolAddress((void**)&Tcp2, g_Tcorr_p2);
    cudaGetSymbolAddress((void**)&Tck, g_Tcorr_k);
    cudaGetSymbolAddress((void**)&Tqdk, g_Tqd_k);
    cudaGetSymbolAddress((void**)&Tcdk, g_Tcd_k);
    cudaGetSymbolAddress((void**)&Wc, g_Wc);
    cudaGetSymbolAddress((void**)&bc, g_bc);
    const float* Wc1 = Wc;
    const float* Wc2 = Wc + 128 * 512;
    const float* bc1 = bc;
    const float* bc2 = bc + 128;

    const int smem_tab  = (128 * 132 + 32 * 128) * 4;
    const int smem_scan = 384 * 132 * 4;
    cudaFuncSetAttribute(tables_all,  cudaFuncAttributeMaxDynamicSharedMemorySize, smem_tab);
    cudaFuncSetAttribute(scan_kernel, cudaFuncAttributeMaxDynamicSharedMemorySize, smem_scan);

    // 1. compose weights/biases
    compose_w<<<dim3(4, 128, 2), 128>>>(Ws1, Ws2, Wx);
    compose_bias<<<1, 256>>>(Ws1, Ws2, bx, bs1, bs2);

    // 2. all 17 table GEMMs in one launch
    JobTable jt;
    const float* Es[17]  = {Eq, Ec, Eqd, Ecd,  Eq, Ec, Eqd, Ecd,  Eq, Ec, Eqd, Ecd,
                            Ecorr, Ecorr, Ecorr, Eqd, Ecd};
    const float* Wsrc[17] = {Wx, Wx + 128, Wx + 256, Wx + 384,
                             Wc1, Wc1 + 128, Wc1 + 256, Wc1 + 384,
                             Wc2, Wc2 + 128, Wc2 + 256, Wc2 + 384,
                             Wp1 + 128, Wp2 + 128, Wk + 128, Wk + 256, Wk + 384};
    const float* Bs[17]  = {nullptr, bx, nullptr, nullptr,
                            nullptr, bc1, nullptr, nullptr,
                            nullptr, bc2, nullptr, nullptr,
                            bp1, bp2, bk, nullptr, nullptr};
    float* Os[17]        = {Tq_x, Tc_x, Tqd_x, Tcd_x,
                            TqA1, TcA1, TqdA1, TcdA1,
                            TqA2, TcA2, TqdA2, TcdA2,
                            Tcp1, Tcp2, Tck, Tqdk, Tcdk};
    int lds[17]          = {512, 512, 512, 512, 512, 512, 512, 512, 512, 512, 512, 512,
                            256, 256, 512, 512, 512};
    int rws[17]          = {NQ, NC, NQD, NCD, NQ, NC, NQD, NCD, NQ, NC, NQD, NCD,
                            2, 2, 2, NQD, NCD};
    int off = 0;
    for (int j = 0; j < 17; j++) {
        jt.E[j] = Es[j]; jt.W[j] = Wsrc[j]; jt.bias[j] = Bs[j];
        jt.out[j] = Os[j]; jt.ld[j] = lds[j]; jt.rows[j] = rws[j];
        jt.blk0[j] = off;
        off += (rws[j] + 31) / 32;
    }
    jt.blk0[17] = off;
    tables_all<<<off, 128, smem_tab>>>(jt);

    // 3. pack streamed weights
    pack_w2<<<128, 256>>>(Wp1, Wp2);
    // 4. dense pre-gather
    pregather<<<dim3(BATCH, TSTEPS), 128>>>(qseq, cseq, qdseq, cdseq, coseq);
    // 5. sequential scan, full 148-SM grid
    scan_kernel<<<148, 384, smem_scan>>>(Ws1, Ws2, Wk, coseq, h0, y);
}

// round 16
// speedup vs baseline: 1.0021x; 1.0021x over previous
#include <cuda_runtime.h>

#define D 128
#define BATCH 1024
#define SEQ 200
#define TSTEPS 199   // S-1

#define NQ 50000
#define NC 1000
#define NQD 101
#define NCD 101

typedef unsigned long long ull;

// ---------------- device scratch ----------------
__device__ float g_Tq_x[NQ * D];
__device__ float g_Tc_x[NC * D];
__device__ float g_Tqd_x[NQD * D];
__device__ float g_Tcd_x[NCD * D];
__device__ float g_TqA1[NQ * D];
__device__ float g_TqA2[NQ * D];
__device__ float g_TcA1[NC * D];
__device__ float g_TcA2[NC * D];
__device__ float g_TqdA1[NQD * D];
__device__ float g_TqdA2[NQD * D];
__device__ float g_TcdA1[NCD * D];
__device__ float g_TcdA2[NCD * D];
__device__ float g_Tcorr_p1[2 * D];
__device__ float g_Tcorr_p2[2 * D];
__device__ float g_Tcorr_k[2 * D];
__device__ float g_Tqd_k[NQD * D];
__device__ float g_Tcd_k[NCD * D];
// composed weights: Wc[z][n][c] = (Wsz @ Wx)[n][c]
__device__ float g_Wc[2 * 128 * 512];
// composed biases
__device__ float g_bc[2 * 128];
// dense pre-gathered scan inputs [t][b][d]
__device__ float g_A1[(size_t)TSTEPS * BATCH * D];
__device__ float g_A2[(size_t)TSTEPS * BATCH * D];
__device__ float g_Ck[(size_t)TSTEPS * BATCH * D];
__device__ float g_Xn[(size_t)TSTEPS * BATCH * D];
// packed k-major interleaved [Wp1a;Wp2a]: (n,k) at float[(k>>2)*1024 + n*4 + (k&3)]
__device__ float g_W2p[256 * D];

// ---------------- f32x2 helpers ----------------
__device__ __forceinline__ void ffma2(ull& acc, ull a, ull b) {
    asm("fma.rn.f32x2 %0, %1, %2, %0;" : "+l"(acc) : "l"(a), "l"(b));
}
__device__ __forceinline__ float unpack_sum(ull v) {
    float lo, hi;
    asm("mov.b64 {%0,%1}, %2;" : "=f"(lo), "=f"(hi) : "l"(v));
    return lo + hi;
}

// ---------------- math helpers ----------------
__device__ __forceinline__ float sigmoidf_(float x) {
    return __fdividef(1.0f, 1.0f + __expf(-x));
}
__device__ __forceinline__ float tanhf_(float x) {
    x = fminf(fmaxf(x, -15.0f), 15.0f);
    float e = __expf(2.0f * x);
    return __fdividef(e - 1.0f, e + 1.0f);
}

// ---------------- compose kernels ----------------
__global__ void __launch_bounds__(128) compose_w(
    const float* __restrict__ Ws1, const float* __restrict__ Ws2,
    const float* __restrict__ Wx)
{
    const float* Ws = blockIdx.z ? Ws2 : Ws1;
    float* out = g_Wc + (size_t)blockIdx.z * 128 * 512;
    int n = blockIdx.y;
    int c = blockIdx.x * 128 + threadIdx.x;
    float s = 0.0f;
#pragma unroll 8
    for (int i = 0; i < 128; i++)
        s = fmaf(Ws[n * 128 + i], Wx[i * 512 + c], s);
    out[n * 512 + c] = s;
}

__global__ void compose_bias(
    const float* __restrict__ Ws1, const float* __restrict__ Ws2,
    const float* __restrict__ bx,
    const float* __restrict__ bs1, const float* __restrict__ bs2)
{
    int tid = threadIdx.x;  // 256
    const float* Ws = (tid < 128) ? Ws1 : Ws2;
    const float* bs = (tid < 128) ? bs1 : bs2;
    int n = tid & 127;
    float s = bs[n];
#pragma unroll 8
    for (int i = 0; i < 128; i++)
        s = fmaf(Ws[n * 128 + i], bx[i], s);
    g_bc[tid] = s;
}

// ---------------- fused table GEMMs (17 jobs, one launch) ----------------
struct JobTable {
    const float* E[17];
    const float* W[17];
    const float* bias[17];
    float*       out[17];
    int          ld[17];
    int          rows[17];
    int          blk0[18];
};

__global__ void __launch_bounds__(128) tables_all(JobTable jt)
{
    int j = 0;
    while ((int)blockIdx.x >= jt.blk0[j + 1]) j++;
    int lb = blockIdx.x - jt.blk0[j];

    const float* E = jt.E[j];
    const float* W = jt.W[j];
    const float* bias = jt.bias[j];
    float* out = jt.out[j];
    int ldW = jt.ld[j];
    int nrows = jt.rows[j];

    extern __shared__ float sm[];
    float* sW = sm;                 // [128][132]
    float* sE = sm + 128 * 132;     // [32][128]
    int tid = threadIdx.x;
    int r0 = lb * 32;
    int rows = nrows - r0; if (rows > 32) rows = 32;

    for (int i = tid; i < 128 * 128; i += 128) {
        int n = i >> 7, k = i & 127;
        sW[n * 132 + k] = W[(size_t)n * ldW + k];
    }
    for (int i = tid; i < rows * 128; i += 128) {
        int m = i >> 7, k = i & 127;
        sE[m * 128 + k] = E[(size_t)(r0 + m) * 128 + k];
    }
    for (int i = tid + rows * 128; i < 32 * 128; i += 128) sE[i] = 0.0f;
    __syncthreads();

    ull acc[32];
#pragma unroll
    for (int m = 0; m < 32; m++) acc[m] = 0ull;

    const ulonglong2* wr = reinterpret_cast<const ulonglong2*>(sW + tid * 132);
#pragma unroll 2
    for (int kc = 0; kc < 32; kc++) {
        ulonglong2 w = wr[kc];
#pragma unroll
        for (int m = 0; m < 32; m++) {
            ulonglong2 e = reinterpret_cast<const ulonglong2*>(sE + m * 128)[kc];
            ffma2(acc[m], e.x, w.x);
            ffma2(acc[m], e.y, w.y);
        }
    }
    float b = (bias != nullptr) ? bias[tid] : 0.0f;
    for (int m = 0; m < rows; m++)
        out[(size_t)(r0 + m) * 128 + tid] = unpack_sum(acc[m]) + b;
}

// ---------------- pack [Wp1a;Wp2a] ----------------
__global__ void pack_w2(const float* __restrict__ Wp1, const float* __restrict__ Wp2)
{
    int i = blockIdx.x * 256 + threadIdx.x;     // 32768 total
    if (i >= 256 * 128) return;
    int n = i >> 7, k = i & 127;
    float v = (n < 128) ? Wp1[n * 256 + k] : Wp2[(n - 128) * 256 + k];
    g_W2p[(k >> 2) * 1024 + n * 4 + (k & 3)] = v;
}

// ---------------- pre-gather dense scan inputs ----------------
__global__ void __launch_bounds__(128) pregather(
    const int* __restrict__ q, const int* __restrict__ c,
    const int* __restrict__ qd, const int* __restrict__ cd,
    const int* __restrict__ corr)
{
    int b = blockIdx.x, t = blockIdx.y, d = threadIdx.x;
    int base = b * SEQ + t;
    int iq = q[base], ic = c[base], iqd = qd[base], icd = cd[base], ico = corr[base];
    int iq2 = q[base + 1], ic2 = c[base + 1], iqd2 = qd[base + 1], icd2 = cd[base + 1];
    size_t o = ((size_t)t * BATCH + b) * D + d;
    g_A1[o] = g_TqA1[iq * D + d] + g_TcA1[ic * D + d] + g_TqdA1[iqd * D + d] + g_TcdA1[icd * D + d];
    g_A2[o] = g_TqA2[iq * D + d] + g_TcA2[ic * D + d] + g_TqdA2[iqd * D + d] + g_TcdA2[icd * D + d];
    g_Ck[o] = g_Tcorr_k[ico * D + d] + g_Tqd_k[iqd * D + d] + g_Tcd_k[icd * D + d];
    g_Xn[o] = g_Tq_x[iq2 * D + d] + g_Tc_x[ic2 * D + d] + g_Tqd_x[iqd2 * D + d] + g_Tcd_x[icd2 * D + d];
}

// ---------------- sequential scan ----------------
// grid 148: CTAs 0..143 -> 7 batch rows, 144..147 -> 4. 384 threads.
// dyn smem: [Ws1; Ws2; Wk1] as [384][132] fp32.
// Phase1 (384 thr): [U(256) | G(128)] = h @ [Ws1;Ws2;Wk1]^T
// EW    (384 thr): sdf, spread over all elements
// Phase2 (256 thr): V(256) = sdf @ [Wp1a;Wp2a]^T (rolling L2 stream)
// Finalize: warp-per-row, shuffle-reduced y dot.

template<int M>
__device__ __forceinline__ void scan_loop(
    const float* __restrict__ smw,
    float (*sh_h)[128], float (*sh_sdf)[128], float (*sh_U)[384],
    float (*sh_cp1)[128], float (*sh_cp2)[128], int* sh_ci,
    int b0, const int* __restrict__ corr_seq,
    const float* __restrict__ h0, float* __restrict__ y)
{
    const int tid = threadIdx.x;
    const int warp = tid >> 5, lane = tid & 31;
    const bool is_p2 = (tid < 256);
    const bool is_fin = (warp < M);
    const ulonglong2* wp = reinterpret_cast<const ulonglong2*>(g_W2p);

    // ew element mapping: e in {tid, tid+384, tid+768}, valid while e < M*128
    int eoff[3]; bool ev[3];
#pragma unroll
    for (int i = 0; i < 3; i++) {
        int e = tid + i * 384;
        ev[i] = (e < M * 128);
        int em = e >> 7, ed = e & 127;
        eoff[i] = (b0 + em) * 128 + ed;
    }
    // finalize mapping: warp = m, lane covers d = lane + 32j
    int foff[4];
#pragma unroll
    for (int j = 0; j < 4; j++)
        foff[j] = (b0 + warp) * 128 + lane + 32 * j;

    for (int i = tid; i < M * 128; i += 384) {
        int m = i >> 7, k = i & 127;
        sh_h[m][k] = h0[(size_t)(b0 + m) * 128 + k];
    }
    if (tid < M) y[(b0 + tid) * SEQ + (SEQ - 1)] = 0.0f;
    __syncthreads();

    for (int t = 0; t < TSTEPS; t++) {
        const size_t tb = (size_t)t * (BATCH * D);
        // ---- stream prefetch (no smem deps; hidden behind phase1)
        float a1v[3], a2v[3];
#pragma unroll
        for (int i = 0; i < 3; i++) if (ev[i]) {
            a1v[i] = g_A1[tb + eoff[i]];
            a2v[i] = g_A2[tb + eoff[i]];
        }
        float ckv[4], xnv[4];
        if (is_fin) {
#pragma unroll
            for (int j = 0; j < 4; j++) {
                ckv[j] = g_Ck[tb + foff[j]];
                xnv[j] = g_Xn[tb + foff[j]];
            }
        }
        if (tid < M) sh_ci[tid] = corr_seq[(b0 + tid) * SEQ + t];

        // ---- Phase1: col = tid over [Ws1;Ws2;Wk1]
        {
            ull acc[M];
#pragma unroll
            for (int m = 0; m < M; m++) acc[m] = 0ull;
            const ulonglong2* wr = reinterpret_cast<const ulonglong2*>(smw + tid * 132);
#pragma unroll 4
            for (int kc = 0; kc < 32; kc++) {
                ulonglong2 w = wr[kc];
#pragma unroll
                for (int m = 0; m < M; m++) {
                    ulonglong2 h2 = reinterpret_cast<const ulonglong2*>(&sh_h[m][0])[kc];
                    ffma2(acc[m], h2.x, w.x);
                    ffma2(acc[m], h2.y, w.y);
                }
            }
#pragma unroll
            for (int m = 0; m < M; m++) sh_U[m][tid] = unpack_sum(acc[m]);
        }
        __syncthreads();

        // ---- EW: sdf over all elements, all threads
#pragma unroll
        for (int i = 0; i < 3; i++) if (ev[i]) {
            int e = tid + i * 384;
            int em = e >> 7, ed = e & 127;
            float s1 = a1v[i] - sh_U[em][ed];
            float s2 = a2v[i] - sh_U[em][ed + 128];
            sh_sdf[em][ed] = sigmoidf_(s1) * tanhf_(s2);
        }
        __syncthreads();

        // ---- Phase2: 256 threads, rolling depth-4 L2 pipeline over W2p
        if (is_p2) {
            ull acc[M];
#pragma unroll
            for (int m = 0; m < M; m++) acc[m] = 0ull;
            ulonglong2 pf[4];
#pragma unroll
            for (int i = 0; i < 4; i++) pf[i] = wp[i * 256 + tid];
#pragma unroll 4
            for (int kc = 0; kc < 32; kc++) {
                ulonglong2 w = pf[kc & 3];
                if (kc < 28) pf[kc & 3] = wp[(kc + 4) * 256 + tid];
#pragma unroll
                for (int m = 0; m < M; m++) {
                    ulonglong2 s2 = reinterpret_cast<const ulonglong2*>(&sh_sdf[m][0])[kc];
                    ffma2(acc[m], s2.x, w.x);
                    ffma2(acc[m], s2.y, w.y);
                }
            }
#pragma unroll
            for (int m = 0; m < M; m++) sh_U[m][tid] = unpack_sum(acc[m]);  // V in U[0:256)
        }
        __syncthreads();

        // ---- Finalize: warp-per-row, 4-way ILP, shuffle reduce
        if (is_fin) {
            const int m = warp;
            const int ci = sh_ci[m];
            float part = 0.0f;
#pragma unroll
            for (int j = 0; j < 4; j++) {
                int d = lane + 32 * j;
                float g   = sigmoidf_(ckv[j] + sh_U[m][d + 256]);
                float p1  = sh_cp1[ci][d] + sh_U[m][d];
                float p2  = sh_cp2[ci][d] + sh_U[m][d + 128];
                float pka = sigmoidf_(p1) * tanhf_(p2);
                float hnew = g * sh_h[m][d] + (1.0f - g) * pka;
                sh_h[m][d] = hnew;
                part = fmaf(xnv[j], hnew, part);
            }
#pragma unroll
            for (int off = 16; off; off >>= 1)
                part += __shfl_down_sync(0xffffffffu, part, off);
            if (lane == 0)
                y[(b0 + m) * SEQ + t] = sigmoidf_(part);
        }
        __syncthreads();
    }
}

__global__ void __launch_bounds__(384, 1) scan_kernel(
    const float* __restrict__ Ws1, const float* __restrict__ Ws2,
    const float* __restrict__ Wk,  const int* __restrict__ corr_seq,
    const float* __restrict__ h0,  float* __restrict__ y)
{
    extern __shared__ float smw[];                       // [384][132]
    __shared__ __align__(16) float sh_h[7][128];
    __shared__ __align__(16) float sh_sdf[7][128];
    __shared__ __align__(16) float sh_U[7][384];
    __shared__ __align__(16) float sh_cp1[2][128];
    __shared__ __align__(16) float sh_cp2[2][128];
    __shared__ int   sh_ci[7];

    int tid = threadIdx.x;
    // weights: rows 0-127 Ws1, 128-255 Ws2, 256-383 Wk[:,0:128]
    for (int i = tid; i < 384 * 128; i += 384) {
        int n = i >> 7, k = i & 127;
        float v;
        if (n < 128)      v = Ws1[n * 128 + k];
        else if (n < 256) v = Ws2[(n - 128) * 128 + k];
        else              v = Wk[(n - 256) * 512 + k];
        smw[n * 132 + k] = v;
    }
    for (int i = tid; i < 256; i += 384) {
        ((float*)sh_cp1)[i] = g_Tcorr_p1[i];
        ((float*)sh_cp2)[i] = g_Tcorr_p2[i];
    }
    // __syncthreads happens inside scan_loop after h0 load.

    if (blockIdx.x < 144)
        scan_loop<7>(smw, sh_h, sh_sdf, sh_U, sh_cp1, sh_cp2, sh_ci,
                     blockIdx.x * 7, corr_seq, h0, y);
    else
        scan_loop<4>(smw, sh_h, sh_sdf, sh_U, sh_cp1, sh_cp2, sh_ci,
                     1008 + (blockIdx.x - 144) * 4, corr_seq, h0, y);
}

// ---------------- host launch ----------------
extern "C" void kernel_launch(void* const* d_in, const int* in_sizes, int n_in,
                              void* d_out, int out_size)
{
    const int*   qseq  = (const int*)  d_in[0];
    const int*   cseq  = (const int*)  d_in[1];
    const int*   qdseq = (const int*)  d_in[2];
    const int*   cdseq = (const int*)  d_in[3];
    const int*   coseq = (const int*)  d_in[4];
    const float* Eq    = (const float*)d_in[5];
    const float* Ec    = (const float*)d_in[6];
    const float* Eqd   = (const float*)d_in[7];
    const float* Ecd   = (const float*)d_in[8];
    const float* Ecorr = (const float*)d_in[9];
    const float* Wx    = (const float*)d_in[10];
    const float* bx    = (const float*)d_in[11];
    const float* Ws1   = (const float*)d_in[12];
    const float* bs1   = (const float*)d_in[13];
    const float* Ws2   = (const float*)d_in[14];
    const float* bs2   = (const float*)d_in[15];
    const float* Wp1   = (const float*)d_in[16];
    const float* bp1   = (const float*)d_in[17];
    const float* Wp2   = (const float*)d_in[18];
    const float* bp2   = (const float*)d_in[19];
    const float* Wk    = (const float*)d_in[20];
    const float* bk    = (const float*)d_in[21];
    const float* h0    = (const float*)d_in[22];
    float* y = (float*)d_out;

    float *Tq_x, *Tc_x, *Tqd_x, *Tcd_x;
    float *TqA1, *TqA2, *TcA1, *TcA2, *TqdA1, *TqdA2, *TcdA1, *TcdA2;
    float *Tcp1, *Tcp2, *Tck, *Tqdk, *Tcdk, *Wc, *bc;
    cudaGetSymbolAddress((void**)&Tq_x, g_Tq_x);
    cudaGetSymbolAddress((void**)&Tc_x, g_Tc_x);
    cudaGetSymbolAddress((void**)&Tqd_x, g_Tqd_x);
    cudaGetSymbolAddress((void**)&Tcd_x, g_Tcd_x);
    cudaGetSymbolAddress((void**)&TqA1, g_TqA1);
    cudaGetSymbolAddress((void**)&TqA2, g_TqA2);
    cudaGetSymbolAddress((void**)&TcA1, g_TcA1);
    cudaGetSymbolAddress((void**)&TcA2, g_TcA2);
    cudaGetSymbolAddress((void**)&TqdA1, g_TqdA1);
    cudaGetSymbolAddress((void**)&TqdA2, g_TqdA2);
    cudaGetSymbolAddress((void**)&TcdA1, g_TcdA1);
    cudaGetSymbolAddress((void**)&TcdA2, g_TcdA2);
    cudaGetSymbolAddress((void**)&Tcp1, g_Tcorr_p1);
    cudaGetSymbolAddress((void**)&Tcp2, g_Tcorr_p2);
    cudaGetSymbolAddress((void**)&Tck, g_Tcorr_k);
    cudaGetSymbolAddress((void**)&Tqdk, g_Tqd_k);
    cudaGetSymbolAddress((void**)&Tcdk, g_Tcd_k);
    cudaGetSymbolAddress((void**)&Wc, g_Wc);
    cudaGetSymbolAddress((void**)&bc, g_bc);
    const float* Wc1 = Wc;
    const float* Wc2 = Wc + 128 * 512;
    const float* bc1 = bc;
    const float* bc2 = bc + 128;

    const int smem_tab  = (128 * 132 + 32 * 128) * 4;
    const int smem_scan = 384 * 132 * 4;
    cudaFuncSetAttribute(tables_all,  cudaFuncAttributeMaxDynamicSharedMemorySize, smem_tab);
    cudaFuncSetAttribute(scan_kernel, cudaFuncAttributeMaxDynamicSharedMemorySize, smem_scan);

    // 1. compose weights/biases
    compose_w<<<dim3(4, 128, 2), 128>>>(Ws1, Ws2, Wx);
    compose_bias<<<1, 256>>>(Ws1, Ws2, bx, bs1, bs2);

    // 2. all 17 table GEMMs in one launch
    JobTable jt;
    const float* Es[17]  = {Eq, Ec, Eqd, Ecd,  Eq, Ec, Eqd, Ecd,  Eq, Ec, Eqd, Ecd,
                            Ecorr, Ecorr, Ecorr, Eqd, Ecd};
    const float* Wsrc[17] = {Wx, Wx + 128, Wx + 256, Wx + 384,
                             Wc1, Wc1 + 128, Wc1 + 256, Wc1 + 384,
                             Wc2, Wc2 + 128, Wc2 + 256, Wc2 + 384,
                             Wp1 + 128, Wp2 + 128, Wk + 128, Wk + 256, Wk + 384};
    const float* Bs[17]  = {nullptr, bx, nullptr, nullptr,
                            nullptr, bc1, nullptr, nullptr,
                            nullptr, bc2, nullptr, nullptr,
                            bp1, bp2, bk, nullptr, nullptr};
    float* Os[17]        = {Tq_x, Tc_x, Tqd_x, Tcd_x,
                            TqA1, TcA1, TqdA1, TcdA1,
                            TqA2, TcA2, TqdA2, TcdA2,
                            Tcp1, Tcp2, Tck, Tqdk, Tcdk};
    int lds[17]          = {512, 512, 512, 512, 512, 512, 512, 512, 512, 512, 512, 512,
                            256, 256, 512, 512, 512};
    int rws[17]          = {NQ, NC, NQD, NCD, NQ, NC, NQD, NCD, NQ, NC, NQD, NCD,
                            2, 2, 2, NQD, NCD};
    int off = 0;
    for (int j = 0; j < 17; j++) {
        jt.E[j] = Es[j]; jt.W[j] = Wsrc[j]; jt.bias[j] = Bs[j];
        jt.out[j] = Os[j]; jt.ld[j] = lds[j]; jt.rows[j] = rws[j];
        jt.blk0[j] = off;
        off += (rws[j] + 31) / 32;
    }
    jt.blk0[17] = off;
    tables_all<<<off, 128, smem_tab>>>(jt);

    // 3. pack streamed weights
    pack_w2<<<128, 256>>>(Wp1, Wp2);
    // 4. dense pre-gather
    pregather<<<dim3(BATCH, TSTEPS), 128>>>(qseq, cseq, qdseq, cdseq, coseq);
    // 5. sequential scan, full 148-SM grid
    scan_kernel<<<148, 384, smem_scan>>>(Ws1, Ws2, Wk, coseq, h0, y);
}